// round 12
// baseline (speedup 1.0000x reference)
#include <cuda_runtime.h>
#include <cuda_bf16.h>
#include <cstdint>

typedef unsigned long long ull;

#define NROWS     262144            // 128 * 2048
#define TILE_ROWS 64
#define NTILES    (NROWS / TILE_ROWS)   // 4096
#define DIM       64
#define KCODES    512
#define GRID      152

// Output layout: [quantized 16777216 | loss 1 | indices 262144]
#define QOFF    0
#define LOSSOFF 16777216
#define IDXOFF  16777217

#define XSTRIDE 68    // padded xn row stride (floats)

__device__ float        g_partials[GRID];
__device__ unsigned int g_count;   // zero-init; reset by last block each launch

// Warp tree-sum: offsets 16,8,4,2,1 — all lanes identical bits.
__device__ __forceinline__ float wsum(float v) {
#pragma unroll
    for (int off = 16; off > 0; off >>= 1)
        v = __fadd_rn(v, __shfl_xor_sync(0xffffffffu, v, off));
    return v;
}

// m16n8k8 TF32 MMA, fp32 accumulate, acc in-place.
__device__ __forceinline__ void mma8(float c[4],
                                     uint32_t a0, uint32_t a1, uint32_t a2, uint32_t a3,
                                     uint32_t b0, uint32_t b1) {
    asm volatile(
        "mma.sync.aligned.m16n8k8.row.col.f32.tf32.tf32.f32 "
        "{%0,%1,%2,%3}, {%4,%5,%6,%7}, {%8,%9}, {%0,%1,%2,%3};"
        : "+f"(c[0]), "+f"(c[1]), "+f"(c[2]), "+f"(c[3])
        : "r"(a0), "r"(a1), "r"(a2), "r"(a3), "r"(b0), "r"(b1));
}

// Exact hi/lo split at tf32 boundary (10 explicit mantissa bits kept).
__device__ __forceinline__ void split(float v, uint32_t& hi, uint32_t& lo) {
    const uint32_t h = __float_as_uint(v) & 0xFFFFE000u;
    hi = h;
    lo = __float_as_uint(__fsub_rn(v, __uint_as_float(h)));
}

// smem layout (bytes):
//   Whi2 : float2[8][512][4]  = 131072   (kt-major: conflict-free LDS.64, no pad)
//   Wlo  : u32  [8][512][4]   =  65536   (packed bf16 pair, conflict-free LDS.32)
//   xnf  : float[64][68]      =  17408
//   B_s  : float[512]         =   2048
//   s_mean/s_den/s_S : 64 f ea =   768
//   s_min: ull[64]            =    512
//   s_loss: float[16] + s_last=     80
#define OFF_WLO   131072
#define OFF_XNF   196608
#define OFF_BS    214016
#define OFF_MEAN  216064
#define OFF_DEN   216320
#define OFF_S     216576
#define OFF_MIN   216832
#define OFF_LOSS  217344
#define OFF_LAST  217408
#define SMEM_BYTES 217600

__global__ __launch_bounds__(512, 1)
void vq_main(const float* __restrict__ x,
             const float* __restrict__ W,
             float* __restrict__ out) {
    extern __shared__ char sraw[];
    float2* Whi2  = reinterpret_cast<float2*>(sraw);
    uint32_t* Wlo = reinterpret_cast<uint32_t*>(sraw + OFF_WLO);
    float* xnf    = reinterpret_cast<float*>(sraw + OFF_XNF);
    float* B_s    = reinterpret_cast<float*>(sraw + OFF_BS);
    float* s_mean = reinterpret_cast<float*>(sraw + OFF_MEAN);
    float* s_den  = reinterpret_cast<float*>(sraw + OFF_DEN);
    float* s_S    = reinterpret_cast<float*>(sraw + OFF_S);
    ull*   s_min  = reinterpret_cast<ull*>(sraw + OFF_MIN);
    float* s_loss = reinterpret_cast<float*>(sraw + OFF_LOSS);
    int*   s_last = reinterpret_cast<int*>(sraw + OFF_LAST);

    const int t    = threadIdx.x;
    const int lane = t & 31;
    const int w    = t >> 5;          // warp 0..15
    const int gid  = lane >> 2;       // 0..7
    const int tig  = lane & 3;        // 0..3
    const int rb   = w & 3;           // row block (16 rows)
    const int cq   = (w >> 2) * 128;  // code quarter base

    // ---- Stage pre-split W fragments (once per block) ----
    for (int i = t; i < KCODES * 32; i += 512) {
        const int n  = i >> 5;
        const int r  = i & 31;
        const int kt = r >> 2;
        const int tg = r & 3;
        const float wa = W[n * 64 + kt * 8 + tg];
        const float wb = W[n * 64 + kt * 8 + tg + 4];
        uint32_t ha, la, hb, lb;
        split(wa, ha, la);
        split(wb, hb, lb);
        Whi2[kt * 2048 + n * 4 + tg] =
            make_float2(__uint_as_float(ha), __uint_as_float(hb));
        const unsigned sa = __bfloat16_as_ushort(__float2bfloat16(__uint_as_float(la)));
        const unsigned sb = __bfloat16_as_ushort(__float2bfloat16(__uint_as_float(lb)));
        Wlo[kt * 2048 + n * 4 + tg] = sa | (sb << 16);
    }

    // ---- B[c] = ||w_c||^2 from exact global W, ascending-k (bit-exact) ----
    {
        float b = 0.0f;
        const float* wr = W + t * 64;
#pragma unroll 16
        for (int k = 0; k < 64; k++)
            b = __fadd_rn(b, __fmul_rn(wr[k], wr[k]));
        B_s[t] = b;
    }

    float loss_acc = 0.0f;

    // ---- prologue stats for first tile ----
    int tile = blockIdx.x;
    {
        const int row0 = tile * TILE_ROWS;
#pragma unroll
        for (int rr = 0; rr < 4; rr++) {
            const int row = 4 * w + rr;
            const float* xr = x + (size_t)(row0 + row) * DIM;
            const float a0 = xr[lane];
            const float a1 = xr[lane + 32];
            const float mean = wsum(__fadd_rn(a0, a1)) * 0.015625f;
            const float c0 = __fsub_rn(a0, mean);
            const float c1 = __fsub_rn(a1, mean);
            const float ss  = wsum(__fadd_rn(__fmul_rn(c0, c0), __fmul_rn(c1, c1)));
            const float den = __fadd_rn(sqrtf(__fdiv_rn(ss, 63.0f)), 1e-7f);
            const float xn0 = __fdiv_rn(c0, den);
            const float xn1 = __fdiv_rn(c1, den);
            const float S = wsum(__fadd_rn(__fmul_rn(xn0, xn0), __fmul_rn(xn1, xn1)));
            xnf[row * XSTRIDE + lane]      = xn0;
            xnf[row * XSTRIDE + lane + 32] = xn1;
            if (lane == 0) {
                s_mean[row] = mean; s_den[row] = den; s_S[row] = S;
                s_min[row]  = ~0ull;
            }
        }
    }
    __syncthreads();

    for (; tile < NTILES; tile += GRID) {
        const int row0 = tile * TILE_ROWS;

        // ---------------- A fragments: 16 rows x K=64, hi/lo split ----------------
        uint32_t ah[8][4], al[8][4];
        {
            const float* p0 = xnf + (rb * 16 + gid) * XSTRIDE + tig;
            const float* p1 = p0 + 8 * XSTRIDE;
#pragma unroll
            for (int kt = 0; kt < 8; kt++) {
                split(p0[kt * 8],     ah[kt][0], al[kt][0]);
                split(p1[kt * 8],     ah[kt][1], al[kt][1]);
                split(p0[kt * 8 + 4], ah[kt][2], al[kt][2]);
                split(p1[kt * 8 + 4], ah[kt][3], al[kt][3]);
            }
        }

        ull best_lo = ~0ull, best_hi = ~0ull;
        const int   row_lo = rb * 16 + gid;
        const float Slo = s_S[row_lo];
        const float Shi = s_S[row_lo + 8];

        // ---------------- 16 n-tiles (8 codes each), 2 at a time ----------------
#pragma unroll 1
        for (int p = 0; p < 8; p++) {
            float chh0[4] = {0, 0, 0, 0}, clo0[4] = {0, 0, 0, 0};
            float chh1[4] = {0, 0, 0, 0}, clo1[4] = {0, 0, 0, 0};
            const int nb = cq + 16 * p + gid;           // b0 code row
            const float2*   hp = Whi2 + nb * 4 + tig;   // +2048 per kt; b1 at +32
            const uint32_t* lp = Wlo  + nb * 4 + tig;
#pragma unroll
            for (int kt = 0; kt < 8; kt++) {
                const float2  h0 = hp[kt * 2048];
                const float2  h1 = hp[kt * 2048 + 32];
                const uint32_t u0 = lp[kt * 2048];
                const uint32_t u1 = lp[kt * 2048 + 32];
                const uint32_t bh0a = __float_as_uint(h0.x);
                const uint32_t bh0b = __float_as_uint(h0.y);
                const uint32_t bh1a = __float_as_uint(h1.x);
                const uint32_t bh1b = __float_as_uint(h1.y);
                const uint32_t bl0a = u0 << 16, bl0b = u0 & 0xFFFF0000u;
                const uint32_t bl1a = u1 << 16, bl1b = u1 & 0xFFFF0000u;
                // interleave: same-accumulator dependent pairs 3 apart
                mma8(clo0, al[kt][0], al[kt][1], al[kt][2], al[kt][3], bh0a, bh0b);
                mma8(clo1, al[kt][0], al[kt][1], al[kt][2], al[kt][3], bh1a, bh1b);
                mma8(chh0, ah[kt][0], ah[kt][1], ah[kt][2], ah[kt][3], bh0a, bh0b);
                mma8(clo0, ah[kt][0], ah[kt][1], ah[kt][2], ah[kt][3], bl0a, bl0b);
                mma8(chh1, ah[kt][0], ah[kt][1], ah[kt][2], ah[kt][3], bh1a, bh1b);
                mma8(clo1, ah[kt][0], ah[kt][1], ah[kt][2], ah[kt][3], bl1a, bl1b);
            }
            // epilogue: distances + running lexicographic min
#pragma unroll
            for (int u = 0; u < 2; u++) {
                const float* chh = u ? chh1 : chh0;
                const float* clo = u ? clo1 : clo0;
                const int cbase = cq + 16 * p + u * 8 + 2 * tig;
                const float B0 = B_s[cbase], B1 = B_s[cbase + 1];
                float d;
                d = __fadd_rn(__fadd_rn(Slo, B0), __fmul_rn(-2.0f, __fadd_rn(chh[0], clo[0])));
                const ull k0 = ((ull)__float_as_uint(d) << 32) | (unsigned)cbase;
                d = __fadd_rn(__fadd_rn(Slo, B1), __fmul_rn(-2.0f, __fadd_rn(chh[1], clo[1])));
                const ull k1 = ((ull)__float_as_uint(d) << 32) | (unsigned)(cbase + 1);
                d = __fadd_rn(__fadd_rn(Shi, B0), __fmul_rn(-2.0f, __fadd_rn(chh[2], clo[2])));
                const ull k2 = ((ull)__float_as_uint(d) << 32) | (unsigned)cbase;
                d = __fadd_rn(__fadd_rn(Shi, B1), __fmul_rn(-2.0f, __fadd_rn(chh[3], clo[3])));
                const ull k3 = ((ull)__float_as_uint(d) << 32) | (unsigned)(cbase + 1);
                if (k0 < best_lo) best_lo = k0;
                if (k1 < best_lo) best_lo = k1;
                if (k2 < best_hi) best_hi = k2;
                if (k3 < best_hi) best_hi = k3;
            }
        }

        // reduce (dist,idx) min across 4-lane group, then across warps
        {
            ull o;
            o = __shfl_xor_sync(0xffffffffu, best_lo, 1); if (o < best_lo) best_lo = o;
            o = __shfl_xor_sync(0xffffffffu, best_lo, 2); if (o < best_lo) best_lo = o;
            o = __shfl_xor_sync(0xffffffffu, best_hi, 1); if (o < best_hi) best_hi = o;
            o = __shfl_xor_sync(0xffffffffu, best_hi, 2); if (o < best_hi) best_hi = o;
            if (tig == 0) {
                atomicMin(&s_min[row_lo],     best_lo);
                atomicMin(&s_min[row_lo + 8], best_hi);
            }
        }
        __syncthreads();

        // ------------- merged phase: output(tile) then stats(tile+GRID) -------------
#pragma unroll
        for (int rr = 0; rr < 4; rr++) {
            const int row = 4 * w + rr;
            const int gr  = row0 + row;
            const int idx = (int)(s_min[row] & 1023ull);
            const float den  = s_den[row];
            const float mean = s_mean[row];
            const float q0 = W[idx * 64 + lane];
            const float q1 = W[idx * 64 + lane + 32];
            const float xn0 = xnf[row * XSTRIDE + lane];
            const float xn1 = xnf[row * XSTRIDE + lane + 32];
            const float e0  = __fsub_rn(q0, xn0);
            const float e1  = __fsub_rn(q1, xn1);
            const float qn0 = __fadd_rn(xn0, e0);
            const float qn1 = __fadd_rn(xn1, e1);
            float* oq = out + QOFF + (size_t)gr * DIM;
            oq[lane]      = __fadd_rn(__fmul_rn(qn0, den), mean);
            oq[lane + 32] = __fadd_rn(__fmul_rn(qn1, den), mean);
            const float ls = wsum(__fadd_rn(__fmul_rn(e0, e0), __fmul_rn(e1, e1)));
            if (lane == 0) {
                out[IDXOFF + gr] = (float)idx;
                loss_acc += ls;
            }
        }

        const int nxt = tile + GRID;
        if (nxt < NTILES) {
            const int nrow0 = nxt * TILE_ROWS;
#pragma unroll
            for (int rr = 0; rr < 4; rr++) {
                const int row = 4 * w + rr;
                const float* xr = x + (size_t)(nrow0 + row) * DIM;
                const float a0 = xr[lane];
                const float a1 = xr[lane + 32];
                const float mean = wsum(__fadd_rn(a0, a1)) * 0.015625f;
                const float c0 = __fsub_rn(a0, mean);
                const float c1 = __fsub_rn(a1, mean);
                const float ss  = wsum(__fadd_rn(__fmul_rn(c0, c0), __fmul_rn(c1, c1)));
                const float den = __fadd_rn(sqrtf(__fdiv_rn(ss, 63.0f)), 1e-7f);
                const float xn0 = __fdiv_rn(c0, den);
                const float xn1 = __fdiv_rn(c1, den);
                const float S = wsum(__fadd_rn(__fmul_rn(xn0, xn0), __fmul_rn(xn1, xn1)));
                xnf[row * XSTRIDE + lane]      = xn0;
                xnf[row * XSTRIDE + lane + 32] = xn1;
                if (lane == 0) {
                    s_mean[row] = mean; s_den[row] = den; s_S[row] = S;
                    s_min[row]  = ~0ull;
                }
            }
        }
        __syncthreads();
    }

    // ---------------- fused deterministic loss finalize (last-block) ----------------
    if (lane == 0) s_loss[w] = loss_acc;
    __syncthreads();
    if (t == 0) {
        float s = 0.0f;
        for (int i = 0; i < 16; i++) s += s_loss[i];
        g_partials[blockIdx.x] = s;
        __threadfence();
        const unsigned tick = atomicAdd(&g_count, 1u);
        *s_last = (tick == gridDim.x - 1);
    }
    __syncthreads();
    if (t == 0 && *s_last) {
        __threadfence();
        float s = 0.0f;
        for (int i = 0; i < (int)gridDim.x; i++) s += g_partials[i];
        out[LOSSOFF] = __fmul_rn(1.25f, __fdiv_rn(s, 16777216.0f));
        g_count = 0;   // reset for next graph replay
    }
}

extern "C" void kernel_launch(void* const* d_in, const int* in_sizes, int n_in,
                              void* d_out, int out_size) {
    const float* x = (const float*)d_in[0];   // [128, 2048, 64] fp32
    const float* W = (const float*)d_in[1];   // [512, 64] fp32
    float* out = (float*)d_out;

    cudaFuncSetAttribute(vq_main, cudaFuncAttributeMaxDynamicSharedMemorySize,
                         SMEM_BYTES);
    vq_main<<<GRID, 512, SMEM_BYTES>>>(x, W, out);
}

// round 13
// speedup vs baseline: 1.0352x; 1.0352x over previous
#include <cuda_runtime.h>
#include <cuda_bf16.h>
#include <cstdint>

typedef unsigned long long ull;

#define NROWS     262144            // 128 * 2048
#define TILE_ROWS 64
#define NTILES    (NROWS / TILE_ROWS)   // 4096
#define DIM       64
#define KCODES    512
#define GRID      152

// Output layout: [quantized 16777216 | loss 1 | indices 262144]
#define QOFF    0
#define LOSSOFF 16777216
#define IDXOFF  16777217

#define XSTRIDE 68    // padded xn row stride (floats)

__device__ float        g_partials[GRID];
__device__ unsigned int g_count;   // zero-init; reset by last block each launch

// Warp tree-sum: offsets 16,8,4,2,1 — all lanes identical bits.
__device__ __forceinline__ float wsum(float v) {
#pragma unroll
    for (int off = 16; off > 0; off >>= 1)
        v = __fadd_rn(v, __shfl_xor_sync(0xffffffffu, v, off));
    return v;
}

// m16n8k8 TF32 MMA, fp32 accumulate, acc in-place.
__device__ __forceinline__ void mma8(float c[4],
                                     uint32_t a0, uint32_t a1, uint32_t a2, uint32_t a3,
                                     uint32_t b0, uint32_t b1) {
    asm volatile(
        "mma.sync.aligned.m16n8k8.row.col.f32.tf32.tf32.f32 "
        "{%0,%1,%2,%3}, {%4,%5,%6,%7}, {%8,%9}, {%0,%1,%2,%3};"
        : "+f"(c[0]), "+f"(c[1]), "+f"(c[2]), "+f"(c[3])
        : "r"(a0), "r"(a1), "r"(a2), "r"(a3), "r"(b0), "r"(b1));
}

// Exact hi/lo split at tf32 boundary.
__device__ __forceinline__ void split(float v, uint32_t& hi, uint32_t& lo) {
    const uint32_t h = __float_as_uint(v) & 0xFFFFE000u;
    hi = h;
    lo = __float_as_uint(__fsub_rn(v, __uint_as_float(h)));
}

// pack two floats as bf16x2 (lo in bits [0:16), hi in [16:32))
__device__ __forceinline__ uint32_t packbf(float f0, float f1) {
    __nv_bfloat162 h = __floats2bfloat162_rn(f0, f1);
    return *reinterpret_cast<uint32_t*>(&h);
}

// smem layout (bytes):
//   Whi2 : float2[8][512][4]  = 131072   (kt-major: conflict-free LDS.64)
//   Wlo  : u32  [8][512][4]   =  65536   (packed bf16 pair)
//   xnf  : float[64][68]      =  17408
//   B_s  : float[512]         =   2048
//   s_mean/s_den/s_S : 64 f ea =   768
//   s_min: ull[64]            =    512
//   s_loss: float[16] + s_last=     80
#define OFF_WLO   131072
#define OFF_XNF   196608
#define OFF_BS    214016
#define OFF_MEAN  216064
#define OFF_DEN   216320
#define OFF_S     216576
#define OFF_MIN   216832
#define OFF_LOSS  217344
#define OFF_LAST  217408
#define SMEM_BYTES 217600

__global__ __launch_bounds__(512, 1)
void vq_main(const float* __restrict__ x,
             const float* __restrict__ W,
             float* __restrict__ out) {
    extern __shared__ char sraw[];
    float2* Whi2  = reinterpret_cast<float2*>(sraw);
    uint32_t* Wlo = reinterpret_cast<uint32_t*>(sraw + OFF_WLO);
    float* xnf    = reinterpret_cast<float*>(sraw + OFF_XNF);
    float* B_s    = reinterpret_cast<float*>(sraw + OFF_BS);
    float* s_mean = reinterpret_cast<float*>(sraw + OFF_MEAN);
    float* s_den  = reinterpret_cast<float*>(sraw + OFF_DEN);
    float* s_S    = reinterpret_cast<float*>(sraw + OFF_S);
    ull*   s_min  = reinterpret_cast<ull*>(sraw + OFF_MIN);
    float* s_loss = reinterpret_cast<float*>(sraw + OFF_LOSS);
    int*   s_last = reinterpret_cast<int*>(sraw + OFF_LAST);

    const int t    = threadIdx.x;
    const int lane = t & 31;
    const int w    = t >> 5;          // warp 0..15
    const int gid  = lane >> 2;       // 0..7
    const int tig  = lane & 3;        // 0..3
    const int rb   = w & 3;           // row block (16 rows)
    const int cq   = (w >> 2) * 128;  // code quarter base

    // ---- Stage pre-split W fragments (once per block) ----
    for (int i = t; i < KCODES * 32; i += 512) {
        const int n  = i >> 5;
        const int r  = i & 31;
        const int kt = r >> 2;
        const int tg = r & 3;
        const float wa = W[n * 64 + kt * 8 + tg];
        const float wb = W[n * 64 + kt * 8 + tg + 4];
        uint32_t ha, la, hb, lb;
        split(wa, ha, la);
        split(wb, hb, lb);
        Whi2[kt * 2048 + n * 4 + tg] =
            make_float2(__uint_as_float(ha), __uint_as_float(hb));
        Wlo[kt * 2048 + n * 4 + tg] =
            packbf(__uint_as_float(la), __uint_as_float(lb));
    }

    // ---- B[c] = ||w_c||^2 from exact global W, ascending-k (bit-exact) ----
    {
        float b = 0.0f;
        const float* wr = W + t * 64;
#pragma unroll 16
        for (int k = 0; k < 64; k++)
            b = __fadd_rn(b, __fmul_rn(wr[k], wr[k]));
        B_s[t] = b;
    }

    float loss_acc = 0.0f;

    // ---- prologue stats for first tile ----
    int tile = blockIdx.x;
    {
        const int row0 = tile * TILE_ROWS;
#pragma unroll
        for (int rr = 0; rr < 4; rr++) {
            const int row = 4 * w + rr;
            const float* xr = x + (size_t)(row0 + row) * DIM;
            const float a0 = xr[lane];
            const float a1 = xr[lane + 32];
            const float mean = wsum(__fadd_rn(a0, a1)) * 0.015625f;
            const float c0 = __fsub_rn(a0, mean);
            const float c1 = __fsub_rn(a1, mean);
            const float ss  = wsum(__fadd_rn(__fmul_rn(c0, c0), __fmul_rn(c1, c1)));
            const float den = __fadd_rn(sqrtf(__fdiv_rn(ss, 63.0f)), 1e-7f);
            const float xn0 = __fdiv_rn(c0, den);
            const float xn1 = __fdiv_rn(c1, den);
            const float S = wsum(__fadd_rn(__fmul_rn(xn0, xn0), __fmul_rn(xn1, xn1)));
            xnf[row * XSTRIDE + lane]      = xn0;
            xnf[row * XSTRIDE + lane + 32] = xn1;
            if (lane == 0) {
                s_mean[row] = mean; s_den[row] = den; s_S[row] = S;
                s_min[row]  = ~0ull;
            }
        }
    }
    __syncthreads();

    for (; tile < NTILES; tile += GRID) {
        const int row0 = tile * TILE_ROWS;

        // ---- A fragments: 16 rows x K=64; hi exact-tf32, lo packed bf16x2 ----
        uint32_t ah[8][4], al2[8][2];
        {
            const float* p0 = xnf + (rb * 16 + gid) * XSTRIDE + tig;
            const float* p1 = p0 + 8 * XSTRIDE;
#pragma unroll
            for (int kt = 0; kt < 8; kt++) {
                uint32_t l0, l1, l2, l3;
                split(p0[kt * 8],     ah[kt][0], l0);
                split(p1[kt * 8],     ah[kt][1], l1);
                split(p0[kt * 8 + 4], ah[kt][2], l2);
                split(p1[kt * 8 + 4], ah[kt][3], l3);
                al2[kt][0] = packbf(__uint_as_float(l0), __uint_as_float(l1));
                al2[kt][1] = packbf(__uint_as_float(l2), __uint_as_float(l3));
            }
        }

        // ---- L2 prefetch of next tile's x rows (lanes 0..7 per warp) ----
        {
            const int nxt = tile + GRID;
            if (nxt < NTILES && lane < 8) {
                const int row = 4 * w + (lane >> 1);
                const float* pf = x + (size_t)(nxt * TILE_ROWS + row) * DIM
                                    + (lane & 1) * 32;
                asm volatile("prefetch.global.L2 [%0];" :: "l"(pf));
            }
        }

        ull best_lo = ~0ull, best_hi = ~0ull;
        const int   row_lo = rb * 16 + gid;
        const float Slo = s_S[row_lo];
        const float Shi = s_S[row_lo + 8];

        // ---------------- 16 n-tiles (8 codes each), 2 at a time ----------------
#pragma unroll 1
        for (int p = 0; p < 8; p++) {
            // 6 independent accumulator chains (each touched once per kt)
            float cHH0[4] = {0,0,0,0}, cHL0[4] = {0,0,0,0}, cLH0[4] = {0,0,0,0};
            float cHH1[4] = {0,0,0,0}, cHL1[4] = {0,0,0,0}, cLH1[4] = {0,0,0,0};
            const int nb = cq + 16 * p + gid;           // b0 code row
            const float2*   hp = Whi2 + nb * 4 + tig;   // +2048 per kt; b1 at +32
            const uint32_t* lp = Wlo  + nb * 4 + tig;
#pragma unroll
            for (int kt = 0; kt < 8; kt++) {
                const float2   h0 = hp[kt * 2048];
                const float2   h1 = hp[kt * 2048 + 32];
                const uint32_t u0 = lp[kt * 2048];
                const uint32_t u1 = lp[kt * 2048 + 32];
                const uint32_t bh0a = __float_as_uint(h0.x);
                const uint32_t bh0b = __float_as_uint(h0.y);
                const uint32_t bh1a = __float_as_uint(h1.x);
                const uint32_t bh1b = __float_as_uint(h1.y);
                const uint32_t bl0a = u0 << 16, bl0b = u0 & 0xFFFF0000u;
                const uint32_t bl1a = u1 << 16, bl1b = u1 & 0xFFFF0000u;
                const uint32_t av0 = al2[kt][0] << 16;
                const uint32_t av1 = al2[kt][0] & 0xFFFF0000u;
                const uint32_t av2 = al2[kt][1] << 16;
                const uint32_t av3 = al2[kt][1] & 0xFFFF0000u;
                mma8(cHH0, ah[kt][0], ah[kt][1], ah[kt][2], ah[kt][3], bh0a, bh0b);
                mma8(cHH1, ah[kt][0], ah[kt][1], ah[kt][2], ah[kt][3], bh1a, bh1b);
                mma8(cLH0, av0, av1, av2, av3,                         bh0a, bh0b);
                mma8(cLH1, av0, av1, av2, av3,                         bh1a, bh1b);
                mma8(cHL0, ah[kt][0], ah[kt][1], ah[kt][2], ah[kt][3], bl0a, bl0b);
                mma8(cHL1, ah[kt][0], ah[kt][1], ah[kt][2], ah[kt][3], bl1a, bl1b);
            }
            // epilogue: distances + running lexicographic min
#pragma unroll
            for (int u = 0; u < 2; u++) {
                const float* chh = u ? cHH1 : cHH0;
                const float* chl = u ? cHL1 : cHL0;
                const float* clh = u ? cLH1 : cLH0;
                const int cbase = cq + 16 * p + u * 8 + 2 * tig;
                const float B0 = B_s[cbase], B1 = B_s[cbase + 1];
                float d, dot;
                dot = __fadd_rn(chh[0], __fadd_rn(chl[0], clh[0]));
                d = __fadd_rn(__fadd_rn(Slo, B0), __fmul_rn(-2.0f, dot));
                const ull k0 = ((ull)__float_as_uint(d) << 32) | (unsigned)cbase;
                dot = __fadd_rn(chh[1], __fadd_rn(chl[1], clh[1]));
                d = __fadd_rn(__fadd_rn(Slo, B1), __fmul_rn(-2.0f, dot));
                const ull k1 = ((ull)__float_as_uint(d) << 32) | (unsigned)(cbase + 1);
                dot = __fadd_rn(chh[2], __fadd_rn(chl[2], clh[2]));
                d = __fadd_rn(__fadd_rn(Shi, B0), __fmul_rn(-2.0f, dot));
                const ull k2 = ((ull)__float_as_uint(d) << 32) | (unsigned)cbase;
                dot = __fadd_rn(chh[3], __fadd_rn(chl[3], clh[3]));
                d = __fadd_rn(__fadd_rn(Shi, B1), __fmul_rn(-2.0f, dot));
                const ull k3 = ((ull)__float_as_uint(d) << 32) | (unsigned)(cbase + 1);
                if (k0 < best_lo) best_lo = k0;
                if (k1 < best_lo) best_lo = k1;
                if (k2 < best_hi) best_hi = k2;
                if (k3 < best_hi) best_hi = k3;
            }
        }

        // reduce (dist,idx) min across 4-lane group, then across warps
        {
            ull o;
            o = __shfl_xor_sync(0xffffffffu, best_lo, 1); if (o < best_lo) best_lo = o;
            o = __shfl_xor_sync(0xffffffffu, best_lo, 2); if (o < best_lo) best_lo = o;
            o = __shfl_xor_sync(0xffffffffu, best_hi, 1); if (o < best_hi) best_hi = o;
            o = __shfl_xor_sync(0xffffffffu, best_hi, 2); if (o < best_hi) best_hi = o;
            if (tig == 0) {
                atomicMin(&s_min[row_lo],     best_lo);
                atomicMin(&s_min[row_lo + 8], best_hi);
            }
        }
        __syncthreads();

        // ------------- merged phase: output(tile) then stats(tile+GRID) -------------
#pragma unroll
        for (int rr = 0; rr < 4; rr++) {
            const int row = 4 * w + rr;
            const int gr  = row0 + row;
            const int idx = (int)(s_min[row] & 1023ull);
            const float den  = s_den[row];
            const float mean = s_mean[row];
            const float q0 = W[idx * 64 + lane];
            const float q1 = W[idx * 64 + lane + 32];
            const float xn0 = xnf[row * XSTRIDE + lane];
            const float xn1 = xnf[row * XSTRIDE + lane + 32];
            const float e0  = __fsub_rn(q0, xn0);
            const float e1  = __fsub_rn(q1, xn1);
            const float qn0 = __fadd_rn(xn0, e0);
            const float qn1 = __fadd_rn(xn1, e1);
            float* oq = out + QOFF + (size_t)gr * DIM;
            oq[lane]      = __fadd_rn(__fmul_rn(qn0, den), mean);
            oq[lane + 32] = __fadd_rn(__fmul_rn(qn1, den), mean);
            const float ls = wsum(__fadd_rn(__fmul_rn(e0, e0), __fmul_rn(e1, e1)));
            if (lane == 0) {
                out[IDXOFF + gr] = (float)idx;
                loss_acc += ls;
            }
        }

        const int nxt = tile + GRID;
        if (nxt < NTILES) {
            const int nrow0 = nxt * TILE_ROWS;
#pragma unroll
            for (int rr = 0; rr < 4; rr++) {
                const int row = 4 * w + rr;
                const float* xr = x + (size_t)(nrow0 + row) * DIM;
                const float a0 = xr[lane];
                const float a1 = xr[lane + 32];
                const float mean = wsum(__fadd_rn(a0, a1)) * 0.015625f;
                const float c0 = __fsub_rn(a0, mean);
                const float c1 = __fsub_rn(a1, mean);
                const float ss  = wsum(__fadd_rn(__fmul_rn(c0, c0), __fmul_rn(c1, c1)));
                const float den = __fadd_rn(sqrtf(__fdiv_rn(ss, 63.0f)), 1e-7f);
                const float xn0 = __fdiv_rn(c0, den);
                const float xn1 = __fdiv_rn(c1, den);
                const float S = wsum(__fadd_rn(__fmul_rn(xn0, xn0), __fmul_rn(xn1, xn1)));
                xnf[row * XSTRIDE + lane]      = xn0;
                xnf[row * XSTRIDE + lane + 32] = xn1;
                if (lane == 0) {
                    s_mean[row] = mean; s_den[row] = den; s_S[row] = S;
                    s_min[row]  = ~0ull;
                }
            }
        }
        __syncthreads();
    }

    // ---------------- fused deterministic loss finalize (last-block) ----------------
    if (lane == 0) s_loss[w] = loss_acc;
    __syncthreads();
    if (t == 0) {
        float s = 0.0f;
        for (int i = 0; i < 16; i++) s += s_loss[i];
        g_partials[blockIdx.x] = s;
        __threadfence();
        const unsigned tick = atomicAdd(&g_count, 1u);
        *s_last = (tick == gridDim.x - 1);
    }
    __syncthreads();
    if (t == 0 && *s_last) {
        __threadfence();
        float s = 0.0f;
        for (int i = 0; i < (int)gridDim.x; i++) s += g_partials[i];
        out[LOSSOFF] = __fmul_rn(1.25f, __fdiv_rn(s, 16777216.0f));
        g_count = 0;   // reset for next graph replay
    }
}

extern "C" void kernel_launch(void* const* d_in, const int* in_sizes, int n_in,
                              void* d_out, int out_size) {
    const float* x = (const float*)d_in[0];   // [128, 2048, 64] fp32
    const float* W = (const float*)d_in[1];   // [512, 64] fp32
    float* out = (float*)d_out;

    cudaFuncSetAttribute(vq_main, cudaFuncAttributeMaxDynamicSharedMemorySize,
                         SMEM_BYTES);
    vq_main<<<GRID, 512, SMEM_BYTES>>>(x, W, out);
}